// round 12
// baseline (speedup 1.0000x reference)
#include <cuda_runtime.h>
#include <cuda_bf16.h>

#define BB 8
#define FF 16384
#define HH 256
#define NROWS (BB*FF)
#define CHUNK 128
#define NCHB  (FF/CHUNK)        // 128 chunks per batch
#define NCHT  (BB*NCHB)         // 1024 chunks total

typedef unsigned long long u64;

// ---------------- scratch (__device__ globals; no allocation) ----------------
__device__ float4 g_cq[NCHT];          // per-chunk quat product
__device__ float  g_cTSC[NCHT*7];      // per-chunk TSC summary
__device__ unsigned int g_barA[BB];    // per-batch monotonic barrier counters
__device__ unsigned int g_barB[BB];

// ---------------- packed f32x2 helpers ----------------
__device__ __forceinline__ u64 pk2(float lo, float hi) {
    u64 r; asm("mov.b64 %0,{%1,%2};" : "=l"(r) : "f"(lo), "f"(hi)); return r;
}
__device__ __forceinline__ void upk2(u64 v, float& lo, float& hi) {
    asm("mov.b64 {%0,%1},%2;" : "=f"(lo), "=f"(hi) : "l"(v));
}
__device__ __forceinline__ u64 ffma2(u64 a, u64 b, u64 c) {
    u64 r; asm("fma.rn.f32x2 %0,%1,%2,%3;" : "=l"(r) : "l"(a), "l"(b), "l"(c)); return r;
}
__device__ __forceinline__ u64 fmul2(u64 a, u64 b) {
    u64 r; asm("mul.rn.f32x2 %0,%1,%2;" : "=l"(r) : "l"(a), "l"(b)); return r;
}
__device__ __forceinline__ float tanha(float x) {
    float r; asm("tanh.approx.f32 %0,%1;" : "=f"(r) : "f"(x)); return r;
}

// quaternion as float4: .x=w, .y..w = vector
__device__ __forceinline__ float4 qmul(float4 q, float4 p) {
    float4 r;
    r.x = q.x*p.x - q.y*p.y - q.z*p.z - q.w*p.w;
    r.y = q.x*p.y + p.x*q.y + (q.z*p.w - q.w*p.z);
    r.z = q.x*p.z + p.x*q.z + (q.w*p.y - q.y*p.w);
    r.w = q.x*p.w + p.x*q.w + (q.y*p.z - q.z*p.y);
    return r;
}
__device__ __forceinline__ float4 shfl_up_q(float4 v, int off) {
    float4 r;
    r.x = __shfl_up_sync(0xffffffffu, v.x, off);
    r.y = __shfl_up_sync(0xffffffffu, v.y, off);
    r.z = __shfl_up_sync(0xffffffffu, v.z, off);
    r.w = __shfl_up_sync(0xffffffffu, v.w, off);
    return r;
}

struct TSC { float T, S0, S1, S2, C0, C1, C2; };
__device__ __forceinline__ TSC tsc_comb(const TSC& l, const TSC& r) {
    TSC o;
    o.C0 = l.C0 + r.C0 + l.S0*r.T;
    o.C1 = l.C1 + r.C1 + l.S1*r.T;
    o.C2 = l.C2 + r.C2 + l.S2*r.T;
    o.S0 = l.S0 + r.S0; o.S1 = l.S1 + r.S1; o.S2 = l.S2 + r.S2;
    o.T  = l.T + r.T;
    return o;
}
__device__ __forceinline__ TSC shfl_up_tsc(const TSC& v, int off) {
    TSC r;
    r.T  = __shfl_up_sync(0xffffffffu, v.T, off);
    r.S0 = __shfl_up_sync(0xffffffffu, v.S0, off);
    r.S1 = __shfl_up_sync(0xffffffffu, v.S1, off);
    r.S2 = __shfl_up_sync(0xffffffffu, v.S2, off);
    r.C0 = __shfl_up_sync(0xffffffffu, v.C0, off);
    r.C1 = __shfl_up_sync(0xffffffffu, v.C1, off);
    r.C2 = __shfl_up_sync(0xffffffffu, v.C2, off);
    return r;
}

// per-batch monotonic grid barrier (n arrivals); replay-safe (no reset)
__device__ __forceinline__ void gbar(unsigned int* bar, unsigned int n) {
    __syncthreads();
    if (threadIdx.x == 0) {
        __threadfence();
        unsigned int my = atomicAdd(bar, 1u) + 1u;
        unsigned int target = ((my + n - 1u) / n) * n;
        while ((int)(*(volatile unsigned int*)bar - target) < 0) __nanosleep(64);
    }
    __syncthreads();
}

// ---------------------------------------------------------------------------
// ONE persistent kernel: MLP (in-reg) -> chunk quat scan -> per-batch barrier
//   -> cross-chunk quat prefix -> accel/rot/TSC scan -> per-batch barrier
//   -> cross-chunk TSC -> pos/vel.  grid = 1024 x 128, all co-resident (7/SM).
// ---------------------------------------------------------------------------
__global__ void __launch_bounds__(128, 7)
imu_kernel(const float* __restrict__ acc, const float* __restrict__ gyro,
           const float* __restrict__ dt,
           const float* __restrict__ init_pos, const float* __restrict__ init_vel,
           const float* __restrict__ init_rot,
           const float* __restrict__ W_enc, const float* __restrict__ b_enc,
           const float* __restrict__ W_dec, const float* __restrict__ b_dec,
           float* __restrict__ out)
{
    __shared__ __align__(16) u64 s_w[128*16];
    __shared__ __align__(16) float4 s_q[128];
    __shared__ __align__(16) float4 s_wq[4];
    __shared__ __align__(16) float4 s_cpre;
    __shared__ TSC s_wt[4];
    __shared__ float s_start[6];

    int j = threadIdx.x, lane = j & 31, wid = j >> 5;
    int c = blockIdx.x;
    int b  = c >> 7;          // batch (NCHB = 128)
    int cb = c & 127;         // chunk within batch
    int e = c*CHUNK + j;      // global row

    // ---- load weights (packed h-pairs) ----
    {
        int p = j;   // 128 threads load 128 pairs
        #pragma unroll
        for (int k = 0; k < 6; k++) {
            const float2 v = reinterpret_cast<const float2*>(W_enc + k*HH)[p];
            s_w[p*16 + k] = pk2(v.x, v.y);
        }
        const float2 bb = reinterpret_cast<const float2*>(b_enc)[p];
        s_w[p*16 + 6] = pk2(bb.x, bb.y);
        #pragma unroll
        for (int k = 0; k < 6; k++) {
            s_w[p*16 + 7 + k] = pk2(W_dec[(2*p)*6 + k], W_dec[(2*p+1)*6 + k]);
        }
        s_w[p*16 + 13] = 0; s_w[p*16 + 14] = 0; s_w[p*16 + 15] = 0;
    }
    __syncthreads();

    // ---- MLP (1 row/thread) ----
    float x0 = acc[e*3+0], x1 = acc[e*3+1], x2 = acc[e*3+2];
    float x3 = gyro[e*3+0], x4 = gyro[e*3+1], x5 = gyro[e*3+2];
    u64 X0 = pk2(x0,x0), X1 = pk2(x1,x1), X2 = pk2(x2,x2);
    u64 X3 = pk2(x3,x3), X4 = pk2(x4,x4), X5 = pk2(x5,x5);

    u64 CU1 = pk2(0.7978845608028654f, 0.7978845608028654f);
    u64 CU3 = pk2(0.035677408136300125f, 0.035677408136300125f);
    u64 HLF = pk2(0.5f, 0.5f);

    u64 a0=0,a1=0,a2=0,a3=0,a4=0,a5=0;

    #pragma unroll 4
    for (int p = 0; p < 128; p++) {
        const ulonglong2* q = reinterpret_cast<const ulonglong2*>(s_w + p*16);
        ulonglong2 q0 = q[0], q1 = q[1], q2 = q[2], q3 = q[3], q4 = q[4], q5 = q[5];
        u64 dec5 = reinterpret_cast<const u64*>(s_w + p*16)[12];

        u64 pre = q3.x;
        pre = ffma2(q0.x, X0, pre);
        pre = ffma2(q0.y, X1, pre);
        pre = ffma2(q1.x, X2, pre);
        pre = ffma2(q1.y, X3, pre);
        pre = ffma2(q2.x, X4, pre);
        pre = ffma2(q2.y, X5, pre);

        u64 s2 = fmul2(pre, pre);
        u64 t2 = ffma2(s2, CU3, CU1);
        u64 up = fmul2(pre, t2);
        float u0f, u1f; upk2(up, u0f, u1f);
        u64 th = pk2(tanha(u0f), tanha(u1f));
        u64 om = ffma2(th, HLF, HLF);
        u64 ft = fmul2(pre, om);

        a0 = ffma2(ft, q3.y, a0);
        a1 = ffma2(ft, q4.x, a1);
        a2 = ffma2(ft, q4.y, a2);
        a3 = ffma2(ft, q5.x, a3);
        a4 = ffma2(ft, q5.y, a4);
        a5 = ffma2(ft, dec5, a5);
    }

    float lo, hi, c0, c1, c2, c3, c4, c5;
    upk2(a0, lo, hi); c0 = lo + hi + __ldg(&b_dec[0]);
    upk2(a1, lo, hi); c1 = lo + hi + __ldg(&b_dec[1]);
    upk2(a2, lo, hi); c2 = lo + hi + __ldg(&b_dec[2]);
    upk2(a3, lo, hi); c3 = lo + hi + __ldg(&b_dec[3]);
    upk2(a4, lo, hi); c4 = lo + hi + __ldg(&b_dec[4]);
    upk2(a5, lo, hi); c5 = lo + hi + __ldg(&b_dec[5]);

    size_t ob = (size_t)e * 16;
    {
        float2* o2 = reinterpret_cast<float2*>(out + ob + 10);
        o2[0] = make_float2(c0, c1);
        o2[1] = make_float2(c2, c3);
        o2[2] = make_float2(c4, c5);
    }
    // corrected acc + delta quat stay IN REGISTERS
    float ca0 = c0 + x0, ca1 = c1 + x1, ca2 = c2 + x2;
    float dtv = dt[e];
    float4 vdq;
    {
        float v0 = (c3 + x3) * dtv;
        float v1 = (c4 + x4) * dtv;
        float v2 = (c5 + x5) * dtv;
        float tt2 = v0*v0 + v1*v1 + v2*v2;
        float theta = sqrtf(tt2 + 1e-16f);
        float half  = 0.5f * theta;
        float w  = cosf(half);
        float sc = (tt2 < 1e-12f) ? (0.5f - tt2 * (1.0f/48.0f)) : (sinf(half) / theta);
        vdq = make_float4(w, v0*sc, v1*sc, v2*sc);
    }

    // ---- Phase A: within-chunk quat scan (128 rows, 4 warps) ----
    float4 v = vdq;
    #pragma unroll
    for (int off = 1; off < 32; off <<= 1) {
        float4 u = shfl_up_q(v, off);
        if (lane >= off) v = qmul(u, v);
    }
    if (lane == 31) s_wq[wid] = v;
    __syncthreads();
    float4 wp = make_float4(1.f, 0.f, 0.f, 0.f);
    for (int wI = 0; wI < wid; wI++) wp = qmul(wp, s_wq[wI]);
    float4 incl = qmul(wp, v);
    s_q[j] = incl;
    if (j == 127) { g_cq[c] = incl; __threadfence(); }

    // ---- per-batch barrier A ----
    gbar(&g_barA[b], NCHB);

    // ---- cross-chunk quat prefix (warp 0; 4 chunks/lane) ----
    if (wid == 0) {
        int base = b*NCHB + 4*lane;
        float4 d0 = __ldcg(&g_cq[base+0]);
        float4 d1 = __ldcg(&g_cq[base+1]);
        float4 d2 = __ldcg(&g_cq[base+2]);
        float4 d3 = __ldcg(&g_cq[base+3]);
        float4 pr = qmul(qmul(d0, d1), qmul(d2, d3));
        #pragma unroll
        for (int off = 1; off < 32; off <<= 1) {
            float4 u = shfl_up_q(pr, off);
            if (lane >= off) pr = qmul(u, pr);
        }
        float4 ex = shfl_up_q(pr, 1);
        float4 q0i = make_float4(init_rot[b*4+0], init_rot[b*4+1],
                                 init_rot[b*4+2], init_rot[b*4+3]);
        float4 pre = (lane == 0) ? q0i : qmul(q0i, ex);
        if (lane == (cb >> 2)) {
            int idx = cb & 3;
            float4 sel = pre;
            if (idx >= 1) sel = qmul(sel, d0);
            if (idx >= 2) sel = qmul(sel, d1);
            if (idx >= 3) sel = qmul(sel, d2);
            s_cpre = sel;
        }
    }
    __syncthreads();

    // ---- Phase B: accel, rot out, within-chunk TSC scan ----
    float4 cpre = s_cpre;
    float4 Ee = (j == 0) ? cpre : qmul(cpre, s_q[j-1]);
    float rn = rsqrtf(Ee.x*Ee.x + Ee.y*Ee.y + Ee.z*Ee.z + Ee.w*Ee.w);
    float qw = Ee.x*rn, q1 = Ee.y*rn, q2 = Ee.z*rn, q3 = Ee.w*rn;

    float t1 = (q2*ca2 - q3*ca1) + qw*ca0;
    float t2 = (q3*ca0 - q1*ca2) + qw*ca1;
    float t3 = (q1*ca1 - q2*ca0) + qw*ca2;
    float aw0 = ca0 + 2.0f*(q2*t3 - q3*t2);
    float aw1 = ca1 + 2.0f*(q3*t1 - q1*t3);
    float aw2 = ca2 + 2.0f*(q1*t2 - q2*t1) - 9.81007f;

    float4 Ei = qmul(cpre, incl);
    float rn2 = rsqrtf(Ei.x*Ei.x + Ei.y*Ei.y + Ei.z*Ei.z + Ei.w*Ei.w);
    {
        float2* r2 = reinterpret_cast<float2*>(out + ob + 6);
        r2[0] = make_float2(Ei.x*rn2, Ei.y*rn2);
        r2[1] = make_float2(Ei.z*rn2, Ei.w*rn2);
    }

    float hd = 0.5f*dtv*dtv;
    TSC tv; tv.T = dtv;
    tv.S0 = aw0*dtv; tv.S1 = aw1*dtv; tv.S2 = aw2*dtv;
    tv.C0 = aw0*hd;  tv.C1 = aw1*hd;  tv.C2 = aw2*hd;

    #pragma unroll
    for (int off = 1; off < 32; off <<= 1) {
        TSC u = shfl_up_tsc(tv, off);
        if (lane >= off) tv = tsc_comb(u, tv);
    }
    if (lane == 31) s_wt[wid] = tv;
    __syncthreads();
    TSC twp; twp.T=0.f; twp.S0=0.f; twp.S1=0.f; twp.S2=0.f; twp.C0=0.f; twp.C1=0.f; twp.C2=0.f;
    for (int wI = 0; wI < wid; wI++) twp = tsc_comb(twp, s_wt[wI]);
    TSC inclT = tsc_comb(twp, tv);
    if (j == 127) {
        g_cTSC[c*7+0]=inclT.T;
        g_cTSC[c*7+1]=inclT.S0; g_cTSC[c*7+2]=inclT.S1; g_cTSC[c*7+3]=inclT.S2;
        g_cTSC[c*7+4]=inclT.C0; g_cTSC[c*7+5]=inclT.C1; g_cTSC[c*7+6]=inclT.C2;
        __threadfence();
    }

    // ---- per-batch barrier B ----
    gbar(&g_barB[b], NCHB);

    // ---- cross-chunk TSC prefix -> own chunk start state (warp 0) ----
    if (wid == 0) {
        int base = b*NCHB + 4*lane;
        TSC d[4];
        #pragma unroll
        for (int k = 0; k < 4; k++) {
            const float* p = &g_cTSC[(base+k)*7];
            d[k].T =__ldcg(p+0);
            d[k].S0=__ldcg(p+1); d[k].S1=__ldcg(p+2); d[k].S2=__ldcg(p+3);
            d[k].C0=__ldcg(p+4); d[k].C1=__ldcg(p+5); d[k].C2=__ldcg(p+6);
        }
        TSC pr = tsc_comb(tsc_comb(d[0], d[1]), tsc_comb(d[2], d[3]));
        #pragma unroll
        for (int off = 1; off < 32; off <<= 1) {
            TSC u = shfl_up_tsc(pr, off);
            if (lane >= off) pr = tsc_comb(u, pr);
        }
        TSC ex = shfl_up_tsc(pr, 1);
        if (lane == 0) { ex.T=0.f; ex.S0=0.f; ex.S1=0.f; ex.S2=0.f; ex.C0=0.f; ex.C1=0.f; ex.C2=0.f; }
        if (lane == (cb >> 2)) {
            int idx = cb & 3;
            TSC sel = ex;
            if (idx >= 1) sel = tsc_comb(sel, d[0]);
            if (idx >= 2) sel = tsc_comb(sel, d[1]);
            if (idx >= 3) sel = tsc_comb(sel, d[2]);
            float ip0 = init_pos[b*3+0], ip1 = init_pos[b*3+1], ip2 = init_pos[b*3+2];
            float iv0 = init_vel[b*3+0], iv1 = init_vel[b*3+1], iv2 = init_vel[b*3+2];
            s_start[0] = ip0 + iv0*sel.T + sel.C0;
            s_start[1] = ip1 + iv1*sel.T + sel.C1;
            s_start[2] = ip2 + iv2*sel.T + sel.C2;
            s_start[3] = iv0 + sel.S0;
            s_start[4] = iv1 + sel.S1;
            s_start[5] = iv2 + sel.S2;
        }
    }
    __syncthreads();

    // ---- Phase C: final pos/vel from in-register TSC ----
    {
        float ps0 = s_start[0], ps1 = s_start[1], ps2 = s_start[2];
        float vs0 = s_start[3], vs1 = s_start[4], vs2 = s_start[5];
        float4* o4 = reinterpret_cast<float4*>(out + ob);
        o4[0] = make_float4(ps0 + vs0*inclT.T + inclT.C0,
                            ps1 + vs1*inclT.T + inclT.C1,
                            ps2 + vs2*inclT.T + inclT.C2,
                            vs0 + inclT.S0);
        reinterpret_cast<float2*>(out + ob + 4)[0] =
            make_float2(vs1 + inclT.S1, vs2 + inclT.S2);
    }
}

// ---------------------------------------------------------------------------
extern "C" void kernel_launch(void* const* d_in, const int* in_sizes, int n_in,
                              void* d_out, int out_size)
{
    const float* acc      = (const float*)d_in[0];
    const float* gyro     = (const float*)d_in[1];
    const float* dt       = (const float*)d_in[2];
    const float* init_pos = (const float*)d_in[3];
    const float* init_vel = (const float*)d_in[4];
    const float* init_rot = (const float*)d_in[5];
    const float* W_enc    = (const float*)d_in[6];
    const float* b_enc    = (const float*)d_in[7];
    const float* W_dec    = (const float*)d_in[8];
    const float* b_dec    = (const float*)d_in[9];
    float* out = (float*)d_out;

    imu_kernel<<<NCHT, CHUNK>>>(acc, gyro, dt, init_pos, init_vel, init_rot,
                                W_enc, b_enc, W_dec, b_dec, out);
}